// round 15
// baseline (speedup 1.0000x reference)
#include <cuda_runtime.h>
#include <cuda_bf16.h>

#define HH 16
#define NN 8192
#define DD 64
#define WW 128
#define NEGV (-1e30f)
#define RS 36          // words per smem plane row (32 data + 4 pad)
#define PLANE 2304     // u32 per plane (64 rows * 36)
#define BUFU 9216      // u32 per buffer (4 planes)
#define SMEM_BYTES (2 * BUFU * 4)

typedef unsigned short u16;
typedef unsigned int u32;

// ---------------- fp32 pooled intermediates ----------------
__device__ float g_k1[HH * 1024 * DD];
__device__ float g_v1[HH * 1024 * DD];
__device__ float g_k2[HH * 128 * DD];
__device__ float g_v2[HH * 128 * DD];
__device__ float g_k3[HH * 16 * DD];
__device__ float g_v3[HH * 16 * DD];

// ---------------- bf16 hi/lo split planes ----------------
__device__ u16 g_kh0[HH * NN * DD],   g_kl0[HH * NN * DD];
__device__ u16 g_vh0[HH * DD * NN],   g_vl0[HH * DD * NN];
__device__ u16 g_kh1[HH * 1024 * DD], g_kl1[HH * 1024 * DD];
__device__ u16 g_vh1[HH * DD * 1024], g_vl1[HH * DD * 1024];
__device__ u16 g_kh2[HH * 128 * DD],  g_kl2[HH * 128 * DD];
__device__ u16 g_vh2[HH * DD * 128],  g_vl2[HH * DD * 128];
__device__ u16 g_kh3[HH * 16 * DD],   g_kl3[HH * 16 * DD];
__device__ u16 g_vh3[HH * DD * 16],   g_vl3[HH * DD * 16];

// ---------------- helpers ----------------
__device__ __forceinline__ void mma_bf16(
    float& d0, float& d1, float& d2, float& d3,
    u32 a0, u32 a1, u32 a2, u32 a3, u32 b0, u32 b1)
{
    asm volatile(
        "mma.sync.aligned.m16n8k16.row.col.f32.bf16.bf16.f32 "
        "{%0,%1,%2,%3}, {%4,%5,%6,%7}, {%8,%9}, {%0,%1,%2,%3};\n"
        : "+f"(d0), "+f"(d1), "+f"(d2), "+f"(d3)
        : "r"(a0), "r"(a1), "r"(a2), "r"(a3), "r"(b0), "r"(b1));
}

__device__ __forceinline__ u32 packbf(float e0, float e1) {
    u32 r; asm("cvt.rn.bf16x2.f32 %0, %1, %2;" : "=r"(r) : "f"(e1), "f"(e0));
    return r;
}
__device__ __forceinline__ void split2(float x0, float x1, u32& hi, u32& lo) {
    hi = packbf(x0, x1);
    float h0 = __uint_as_float(hi << 16);
    float h1 = __uint_as_float(hi & 0xffff0000u);
    lo = packbf(x0 - h0, x1 - h1);
}

__device__ __forceinline__ void cp16(const void* smem_dst, const void* gsrc) {
    unsigned sa = (unsigned)__cvta_generic_to_shared(smem_dst);
    asm volatile("cp.async.cg.shared.global [%0], [%1], 16;" :: "r"(sa), "l"(gsrc));
}
__device__ __forceinline__ void cp_commit() {
    asm volatile("cp.async.commit_group;" ::: "memory");
}
__device__ __forceinline__ void cp_wait_all() {
    asm volatile("cp.async.wait_group 0;" ::: "memory");
}

// ---------------- fused split + transpose + pool kernel ----------------
__global__ void fuse_kernel(const float* __restrict__ ksrc,
                            const float* __restrict__ vsrc, int C,
                            u16* __restrict__ khi, u16* __restrict__ klo,
                            u16* __restrict__ vhi, u16* __restrict__ vlo,
                            float* __restrict__ kpool, float* __restrict__ vpool)
{
    __shared__ float skf[32][65], svf[32][65];
    int h = blockIdx.y, k0 = blockIdx.x * 32;
    int tid = threadIdx.x;
#pragma unroll
    for (int it = 0; it < 2; it++) {
        int e = tid + it * 256;
        int row = e >> 4, f4 = e & 15;
        float4 a = make_float4(0.f, 0.f, 0.f, 0.f), b = a;
        if (k0 + row < C) {
            a = reinterpret_cast<const float4*>(ksrc + ((size_t)h * C + k0 + row) * DD)[f4];
            b = reinterpret_cast<const float4*>(vsrc + ((size_t)h * C + k0 + row) * DD)[f4];
        }
        skf[row][f4 * 4 + 0] = a.x; skf[row][f4 * 4 + 1] = a.y;
        skf[row][f4 * 4 + 2] = a.z; skf[row][f4 * 4 + 3] = a.w;
        svf[row][f4 * 4 + 0] = b.x; svf[row][f4 * 4 + 1] = b.y;
        svf[row][f4 * 4 + 2] = b.z; svf[row][f4 * 4 + 3] = b.w;
    }
    __syncthreads();
#pragma unroll
    for (int it = 0; it < 4; it++) {
        int idx = tid + it * 256;
        int key = idx >> 5, dp = (idx & 31) * 2;
        if (k0 + key < C) {
            u32 hi, lo;
            split2(skf[key][dp], skf[key][dp + 1], hi, lo);
            size_t w = ((size_t)h * C + k0 + key) * 32 + (idx & 31);
            reinterpret_cast<u32*>(khi)[w] = hi;
            reinterpret_cast<u32*>(klo)[w] = lo;
        }
    }
#pragma unroll
    for (int it = 0; it < 4; it++) {
        int idx = tid + it * 256;
        int d = idx >> 4, kp = (idx & 15) * 2;
        if (k0 + kp < C) {
            u32 hi, lo;
            split2(svf[kp][d], svf[kp + 1][d], hi, lo);
            size_t w = (((size_t)h * DD + d) * C + k0 + kp) >> 1;
            reinterpret_cast<u32*>(vhi)[w] = hi;
            reinterpret_cast<u32*>(vlo)[w] = lo;
        }
    }
    if (kpool != nullptr) {
        int chunk = tid >> 6, d = tid & 63;
        float sk = 0.f, sv = 0.f;
#pragma unroll
        for (int r = 0; r < 8; r++) {
            sk += skf[chunk * 8 + r][d];
            sv += svf[chunk * 8 + r][d];
        }
        size_t w = ((size_t)h * (C / 8) + (k0 >> 3) + chunk) * DD + d;
        kpool[w] = sk * 0.125f;
        vpool[w] = sv * 0.125f;
    }
}

// ---------------- 64-key tile prefetch (128 threads) ----------------
__device__ __forceinline__ void prefetch64(
    u32* sm, int buf,
    const u16* __restrict__ khg, const u16* __restrict__ klg,
    const u16* __restrict__ vhg, const u16* __restrict__ vlg,
    int C, int tb, int tid)
{
    u32* kh = sm + buf * BUFU;
    u32* kl = kh + PLANE;
    u32* vh = kl + PLANE;
    u32* vl = vh + PLANE;
#pragma unroll
    for (int t = 0; t < 4; t++) {
        int e = tid + t * 128;             // [0, 512)
        int row = e >> 3, ch = e & 7;
        int r = tb + row;
        r = r < 0 ? 0 : (r > C - 1 ? C - 1 : r);
        size_t so = (size_t)r * 32 + ch * 4;
        cp16(kh + row * RS + ch * 4, (const u32*)khg + so);
        cp16(kl + row * RS + ch * 4, (const u32*)klg + so);
    }
#pragma unroll
    for (int t = 0; t < 4; t++) {
        int e = tid + t * 128;             // [0, 512)
        int d = e >> 3, ch = e & 7;
        int k0 = tb + ch * 8;
        k0 = k0 < 0 ? 0 : (k0 > C - 8 ? C - 8 : k0);
        size_t so = ((size_t)d * C + k0) >> 1;
        cp16(vh + d * RS + ch * 4, (const u32*)vhg + so);
        cp16(vl + d * RS + ch * 4, (const u32*)vlg + so);
    }
    cp_commit();
}

// ---------------- FA2 bf16-split attention, M-blocked warps ----------------
// CTA = 128 queries x 1 head, 128 threads / 4 warps; warp owns 32 rows as two
// m16 row-blocks sharing every B-fragment load (halves smem read volume).

__global__ void __launch_bounds__(128, 2) attn_kernel(
    const float* __restrict__ q, const float* __restrict__ gammas,
    float* __restrict__ out)
{
    extern __shared__ u32 sm[];

    int h = blockIdx.y;
    int qtile = (int)(gridDim.x - 1u - blockIdx.x);   // heavy tiles first
    int qs = qtile * 128;
    int tid = threadIdx.x;
    int warp = tid >> 5, lane = tid & 31;
    int r0 = qs + warp * 32;
    int g = lane >> 2, c = lane & 3;
    int cc = 2 * c;
    int i0 = r0 + g, i1 = i0 + 8, i2 = i0 + 16, i3 = i0 + 24;

    // Q split once for both row-blocks
    u32 qh0[4][4], ql0[4][4], qh1[4][4], ql1[4][4];
    {
        const float* p0 = q + ((size_t)h * NN + i0) * DD;
        const float* p1 = q + ((size_t)h * NN + i1) * DD;
        const float* p2 = q + ((size_t)h * NN + i2) * DD;
        const float* p3 = q + ((size_t)h * NN + i3) * DD;
#pragma unroll
        for (int ks = 0; ks < 4; ks++) {
            split2(p0[16 * ks + cc],     p0[16 * ks + cc + 1], qh0[ks][0], ql0[ks][0]);
            split2(p1[16 * ks + cc],     p1[16 * ks + cc + 1], qh0[ks][1], ql0[ks][1]);
            split2(p0[16 * ks + cc + 8], p0[16 * ks + cc + 9], qh0[ks][2], ql0[ks][2]);
            split2(p1[16 * ks + cc + 8], p1[16 * ks + cc + 9], qh0[ks][3], ql0[ks][3]);
            split2(p2[16 * ks + cc],     p2[16 * ks + cc + 1], qh1[ks][0], ql1[ks][0]);
            split2(p3[16 * ks + cc],     p3[16 * ks + cc + 1], qh1[ks][1], ql1[ks][1]);
            split2(p2[16 * ks + cc + 8], p2[16 * ks + cc + 9], qh1[ks][2], ql1[ks][2]);
            split2(p3[16 * ks + cc + 8], p3[16 * ks + cc + 9], qh1[ks][3], ql1[ks][3]);
        }
    }

    float m0 = NEGV, m1 = NEGV, m2 = NEGV, m3 = NEGV;
    float l0 = 0.f, l1 = 0.f, l2 = 0.f, l3 = 0.f;
    float O0[8][4], O1[8][4];
#pragma unroll
    for (int n = 0; n < 8; n++) {
        O0[n][0] = O0[n][1] = O0[n][2] = O0[n][3] = 0.f;
        O1[n][0] = O1[n][1] = O1[n][2] = O1[n][3] = 0.f;
    }

    float gm[4] = { __ldg(&gammas[0]), __ldg(&gammas[1]),
                    __ldg(&gammas[2]), __ldg(&gammas[3]) };
    const float scale = 0.125f;

    auto do_half = [&](const u32* kbh, const u32* kbl, const u32* vbh, const u32* vbl,
                       bool L0, int base, int S, float gamma) {
        float s0[4][4], s1[4][4];
#pragma unroll
        for (int n = 0; n < 4; n++) {
            s0[n][0] = s0[n][1] = s0[n][2] = s0[n][3] = 0.f;
            s1[n][0] = s1[n][1] = s1[n][2] = s1[n][3] = 0.f;
        }

        // ---- QK^T: shared B-frag, 6 MMAs per load ----
#pragma unroll
        for (int nb = 0; nb < 4; nb++) {
            const u32* ph = kbh + (nb * 8 + g) * RS + c;
            const u32* pl = kbl + (nb * 8 + g) * RS + c;
#pragma unroll
            for (int ks = 0; ks < 4; ks++) {
                u32 bh0 = ph[8 * ks], bh1 = ph[8 * ks + 4];
                u32 bl0 = pl[8 * ks], bl1 = pl[8 * ks + 4];
                mma_bf16(s0[nb][0], s0[nb][1], s0[nb][2], s0[nb][3],
                         qh0[ks][0], qh0[ks][1], qh0[ks][2], qh0[ks][3], bh0, bh1);
                mma_bf16(s0[nb][0], s0[nb][1], s0[nb][2], s0[nb][3],
                         qh0[ks][0], qh0[ks][1], qh0[ks][2], qh0[ks][3], bl0, bl1);
                mma_bf16(s0[nb][0], s0[nb][1], s0[nb][2], s0[nb][3],
                         ql0[ks][0], ql0[ks][1], ql0[ks][2], ql0[ks][3], bh0, bh1);
                mma_bf16(s1[nb][0], s1[nb][1], s1[nb][2], s1[nb][3],
                         qh1[ks][0], qh1[ks][1], qh1[ks][2], qh1[ks][3], bh0, bh1);
                mma_bf16(s1[nb][0], s1[nb][1], s1[nb][2], s1[nb][3],
                         qh1[ks][0], qh1[ks][1], qh1[ks][2], qh1[ks][3], bl0, bl1);
                mma_bf16(s1[nb][0], s1[nb][1], s1[nb][2], s1[nb][3],
                         ql1[ks][0], ql1[ks][1], ql1[ks][2], ql1[ks][3], bh0, bh1);
            }
        }

        // ---- mask + ALiBi bias, both row-blocks ----
#pragma unroll
        for (int n = 0; n < 4; n++) {
            int colA = 8 * n + cc;
            if (L0) {
                int jA = base + colA, jB = jA + 1;
                int dA0 = i0 - jA, dB0 = dA0 - 1;
                s0[n][0] = (jA >= 0 && (unsigned)dA0 < WW) ? fmaf(s0[n][0], scale, -gamma * (float)dA0) : NEGV;
                s0[n][1] = (jB >= 0 && (unsigned)dB0 < WW) ? fmaf(s0[n][1], scale, -gamma * (float)dB0) : NEGV;
                int dA1 = dA0 + 8, dB1 = dB0 + 8;
                s0[n][2] = (jA >= 0 && (unsigned)dA1 < WW) ? fmaf(s0[n][2], scale, -gamma * (float)dA1) : NEGV;
                s0[n][3] = (jB >= 0 && (unsigned)dB1 < WW) ? fmaf(s0[n][3], scale, -gamma * (float)dB1) : NEGV;
                int dA2 = dA0 + 16, dB2 = dB0 + 16;
                s1[n][0] = (jA >= 0 && (unsigned)dA2 < WW) ? fmaf(s1[n][0], scale, -gamma * (float)dA2) : NEGV;
                s1[n][1] = (jB >= 0 && (unsigned)dB2 < WW) ? fmaf(s1[n][1], scale, -gamma * (float)dB2) : NEGV;
                int dA3 = dA0 + 24, dB3 = dB0 + 24;
                s1[n][2] = (jA >= 0 && (unsigned)dA3 < WW) ? fmaf(s1[n][2], scale, -gamma * (float)dA3) : NEGV;
                s1[n][3] = (jB >= 0 && (unsigned)dB3 < WW) ? fmaf(s1[n][3], scale, -gamma * (float)dB3) : NEGV;
            } else {
                int jlA = (base + colA + 1) * S - 1;
                int jlB = jlA + S;
                int dA0 = i0 - jlA, dB0 = i0 - jlB;
                s0[n][0] = (dA0 >= WW) ? fmaf(s0[n][0], scale, -gamma * (float)dA0) : NEGV;
                s0[n][1] = (dB0 >= WW) ? fmaf(s0[n][1], scale, -gamma * (float)dB0) : NEGV;
                int dA1 = dA0 + 8, dB1 = dB0 + 8;
                s0[n][2] = (dA1 >= WW) ? fmaf(s0[n][2], scale, -gamma * (float)dA1) : NEGV;
                s0[n][3] = (dB1 >= WW) ? fmaf(s0[n][3], scale, -gamma * (float)dB1) : NEGV;
                int dA2 = dA0 + 16, dB2 = dB0 + 16;
                s1[n][0] = (dA2 >= WW) ? fmaf(s1[n][0], scale, -gamma * (float)dA2) : NEGV;
                s1[n][1] = (dB2 >= WW) ? fmaf(s1[n][1], scale, -gamma * (float)dB2) : NEGV;
                int dA3 = dA0 + 24, dB3 = dB0 + 24;
                s1[n][2] = (dA3 >= WW) ? fmaf(s1[n][2], scale, -gamma * (float)dA3) : NEGV;
                s1[n][3] = (dB3 >= WW) ? fmaf(s1[n][3], scale, -gamma * (float)dB3) : NEGV;
            }
        }

        // ---- online softmax (4 row-sets) ----
        float ml0 = s0[0][0], ml1 = s0[0][2], ml2 = s1[0][0], ml3 = s1[0][2];
#pragma unroll
        for (int n = 0; n < 4; n++) {
            ml0 = fmaxf(ml0, fmaxf(s0[n][0], s0[n][1]));
            ml1 = fmaxf(ml1, fmaxf(s0[n][2], s0[n][3]));
            ml2 = fmaxf(ml2, fmaxf(s1[n][0], s1[n][1]));
            ml3 = fmaxf(ml3, fmaxf(s1[n][2], s1[n][3]));
        }
        ml0 = fmaxf(ml0, __shfl_xor_sync(0xffffffffu, ml0, 1));
        ml0 = fmaxf(ml0, __shfl_xor_sync(0xffffffffu, ml0, 2));
        ml1 = fmaxf(ml1, __shfl_xor_sync(0xffffffffu, ml1, 1));
        ml1 = fmaxf(ml1, __shfl_xor_sync(0xffffffffu, ml1, 2));
        ml2 = fmaxf(ml2, __shfl_xor_sync(0xffffffffu, ml2, 1));
        ml2 = fmaxf(ml2, __shfl_xor_sync(0xffffffffu, ml2, 2));
        ml3 = fmaxf(ml3, __shfl_xor_sync(0xffffffffu, ml3, 1));
        ml3 = fmaxf(ml3, __shfl_xor_sync(0xffffffffu, ml3, 2));
        float nm0 = fmaxf(m0, ml0), nm1 = fmaxf(m1, ml1);
        float nm2 = fmaxf(m2, ml2), nm3 = fmaxf(m3, ml3);
        float e0 = __expf(m0 - nm0), e1 = __expf(m1 - nm1);
        float e2 = __expf(m2 - nm2), e3 = __expf(m3 - nm3);
        m0 = nm0; m1 = nm1; m2 = nm2; m3 = nm3;
        float sum0 = 0.f, sum1 = 0.f, sum2 = 0.f, sum3 = 0.f;
#pragma unroll
        for (int n = 0; n < 4; n++) {
            s0[n][0] = __expf(s0[n][0] - nm0); sum0 += s0[n][0];
            s0[n][1] = __expf(s0[n][1] - nm0); sum0 += s0[n][1];
            s0[n][2] = __expf(s0[n][2] - nm1); sum1 += s0[n][2];
            s0[n][3] = __expf(s0[n][3] - nm1); sum1 += s0[n][3];
            s1[n][0] = __expf(s1[n][0] - nm2); sum2 += s1[n][0];
            s1[n][1] = __expf(s1[n][1] - nm2); sum2 += s1[n][1];
            s1[n][2] = __expf(s1[n][2] - nm3); sum3 += s1[n][2];
            s1[n][3] = __expf(s1[n][3] - nm3); sum3 += s1[n][3];
        }
        l0 = fmaf(l0, e0, sum0);
        l1 = fmaf(l1, e1, sum1);
        l2 = fmaf(l2, e2, sum2);
        l3 = fmaf(l3, e3, sum3);
        if (!__all_sync(0xffffffffu,
                        (e0 == 1.f) && (e1 == 1.f) && (e2 == 1.f) && (e3 == 1.f))) {
#pragma unroll
            for (int n = 0; n < 8; n++) {
                O0[n][0] *= e0; O0[n][1] *= e0; O0[n][2] *= e1; O0[n][3] *= e1;
                O1[n][0] *= e2; O1[n][1] *= e2; O1[n][2] *= e3; O1[n][3] *= e3;
            }
        }

        // ---- O += P V : shared V-frag, 6 MMAs per load ----
#pragma unroll
        for (int kt = 0; kt < 2; kt++) {
            u32 A0h[4], A0l[4], A1h[4], A1l[4];
            split2(s0[2 * kt][0],     s0[2 * kt][1],     A0h[0], A0l[0]);
            split2(s0[2 * kt][2],     s0[2 * kt][3],     A0h[1], A0l[1]);
            split2(s0[2 * kt + 1][0], s0[2 * kt + 1][1], A0h[2], A0l[2]);
            split2(s0[2 * kt + 1][2], s0[2 * kt + 1][3], A0h[3], A0l[3]);
            split2(s1[2 * kt][0],     s1[2 * kt][1],     A1h[0], A1l[0]);
            split2(s1[2 * kt][2],     s1[2 * kt][3],     A1h[1], A1l[1]);
            split2(s1[2 * kt + 1][0], s1[2 * kt + 1][1], A1h[2], A1l[2]);
            split2(s1[2 * kt + 1][2], s1[2 * kt + 1][3], A1h[3], A1l[3]);
#pragma unroll
            for (int nb = 0; nb < 8; nb++) {
                const u32* ph = vbh + (nb * 8 + g) * RS + c;
                const u32* pl = vbl + (nb * 8 + g) * RS + c;
                u32 bh0 = ph[8 * kt], bh1 = ph[8 * kt + 4];
                u32 bl0 = pl[8 * kt], bl1 = pl[8 * kt + 4];
                mma_bf16(O0[nb][0], O0[nb][1], O0[nb][2], O0[nb][3],
                         A0h[0], A0h[1], A0h[2], A0h[3], bh0, bh1);
                mma_bf16(O0[nb][0], O0[nb][1], O0[nb][2], O0[nb][3],
                         A0h[0], A0h[1], A0h[2], A0h[3], bl0, bl1);
                mma_bf16(O0[nb][0], O0[nb][1], O0[nb][2], O0[nb][3],
                         A0l[0], A0l[1], A0l[2], A0l[3], bh0, bh1);
                mma_bf16(O1[nb][0], O1[nb][1], O1[nb][2], O1[nb][3],
                         A1h[0], A1h[1], A1h[2], A1h[3], bh0, bh1);
                mma_bf16(O1[nb][0], O1[nb][1], O1[nb][2], O1[nb][3],
                         A1h[0], A1h[1], A1h[2], A1h[3], bl0, bl1);
                mma_bf16(O1[nb][0], O1[nb][1], O1[nb][2], O1[nb][3],
                         A1l[0], A1l[1], A1l[2], A1l[3], bh0, bh1);
            }
        }
    };

#pragma unroll 1
    for (int lvl = 0; lvl < 4; lvl++) {
        const u16 *khg, *klg, *vhg, *vlg;
        int C, S, n, ntv = 0;
        float gamma = gm[lvl];
        bool L0 = (lvl == 0);
        if (lvl == 0) {
            khg = g_kh0 + (size_t)h * NN * DD;  klg = g_kl0 + (size_t)h * NN * DD;
            vhg = g_vh0 + (size_t)h * DD * NN;  vlg = g_vl0 + (size_t)h * DD * NN;
            C = NN; S = 1;
            n = qs / 64 + 2; if (n > 4) n = 4;
        } else {
            if (lvl == 1) {
                khg = g_kh1 + (size_t)h * 1024 * DD; klg = g_kl1 + (size_t)h * 1024 * DD;
                vhg = g_vh1 + (size_t)h * DD * 1024; vlg = g_vl1 + (size_t)h * DD * 1024;
                C = 1024; S = 8;
            } else if (lvl == 2) {
                khg = g_kh2 + (size_t)h * 128 * DD;  klg = g_kl2 + (size_t)h * 128 * DD;
                vhg = g_vh2 + (size_t)h * DD * 128;  vlg = g_vl2 + (size_t)h * DD * 128;
                C = 128; S = 64;
            } else {
                khg = g_kh3 + (size_t)h * 16 * DD;   klg = g_kl3 + (size_t)h * 16 * DD;
                vhg = g_vh3 + (size_t)h * DD * 16;   vlg = g_vl3 + (size_t)h * DD * 16;
                C = 16; S = 512;
            }
            int cmax = qs / S - 1;
            if (cmax < 0) { continue; }
            ntv = cmax / 64 + 1;
            int dcut = (int)(24.0f / gamma);
            n = 0;
#pragma unroll 1
            for (int it = 0; it < ntv; it++) {
                int cb = (ntv - 1 - it) * 64;
                if (qs - ((cb + 64) * S - 1) <= dcut) n++;
                else break;
            }
            if (n <= 0) continue;
        }

        int cwmax = 0x7fffffff;
        if (!L0) cwmax = (r0 >= 96 + S) ? ((r0 - 96) / S - 1) : -1;
        int dcutw = L0 ? 0 : (int)(24.0f / gamma);

        __syncthreads();
        int tb0 = L0 ? (qs + 128 - 64) : ((ntv - 1) * 64);
        prefetch64(sm, 0, khg, klg, vhg, vlg, C, tb0, tid);
#pragma unroll 1
        for (int it = 0; it < n; it++) {
            int buf = it & 1;
            int tb = L0 ? (qs + 128 - 64 * (it + 1)) : ((ntv - 1 - it) * 64);
            cp_wait_all();
            __syncthreads();
            if (it + 1 < n) {
                int tb1 = L0 ? (qs + 128 - 64 * (it + 2)) : ((ntv - 2 - it) * 64);
                prefetch64(sm, (it + 1) & 1, khg, klg, vhg, vlg, C, tb1, tid);
            }
            const u32* kb = sm + buf * BUFU;
            const u32* klb = kb + PLANE;
            const u32* vb = klb + PLANE;
            const u32* vlb = vb + PLANE;
#pragma unroll
            for (int hf = 1; hf >= 0; hf--) {
                int base = tb + 32 * hf;
                if (L0) {
                    if (base > r0 + 31 || base + 31 < r0 - (WW - 1)) continue;
                } else {
                    if (base > cwmax) continue;
                    if (r0 - ((base + 32) * S - 1) > dcutw) continue;
                }
                do_half(kb + hf * 32 * RS, klb + hf * 32 * RS,
                        vb + hf * 16, vlb + hf * 16, L0, base, S, gamma);
            }
        }
    }

    // ================= epilogue: out = O / clip(l, 1e-8) =================
    l0 += __shfl_xor_sync(0xffffffffu, l0, 1);
    l0 += __shfl_xor_sync(0xffffffffu, l0, 2);
    l1 += __shfl_xor_sync(0xffffffffu, l1, 1);
    l1 += __shfl_xor_sync(0xffffffffu, l1, 2);
    l2 += __shfl_xor_sync(0xffffffffu, l2, 1);
    l2 += __shfl_xor_sync(0xffffffffu, l2, 2);
    l3 += __shfl_xor_sync(0xffffffffu, l3, 1);
    l3 += __shfl_xor_sync(0xffffffffu, l3, 2);
    float inv0 = 1.0f / fmaxf(l0, 1e-8f);
    float inv1 = 1.0f / fmaxf(l1, 1e-8f);
    float inv2 = 1.0f / fmaxf(l2, 1e-8f);
    float inv3 = 1.0f / fmaxf(l3, 1e-8f);
    float* p0 = out + ((size_t)h * NN + i0) * DD;
    float* p1 = out + ((size_t)h * NN + i1) * DD;
    float* p2 = out + ((size_t)h * NN + i2) * DD;
    float* p3 = out + ((size_t)h * NN + i3) * DD;
#pragma unroll
    for (int n = 0; n < 8; n++) {
        *reinterpret_cast<float2*>(p0 + 8 * n + cc) = make_float2(O0[n][0] * inv0, O0[n][1] * inv0);
        *reinterpret_cast<float2*>(p1 + 8 * n + cc) = make_float2(O0[n][2] * inv1, O0[n][3] * inv1);
        *reinterpret_cast<float2*>(p2 + 8 * n + cc) = make_float2(O1[n][0] * inv2, O1[n][1] * inv2);
        *reinterpret_cast<float2*>(p3 + 8 * n + cc) = make_float2(O1[n][2] * inv3, O1[n][3] * inv3);
    }
}

// ---------------- launch ----------------
extern "C" void kernel_launch(void* const* d_in, const int* in_sizes, int n_in,
                              void* d_out, int out_size) {
    const float* q      = (const float*)d_in[0];
    const float* k      = (const float*)d_in[1];
    const float* v      = (const float*)d_in[2];
    const float* gammas = (const float*)d_in[3];
    float* out = (float*)d_out;

    u16 *kh0, *kl0, *vh0, *vl0, *kh1, *kl1, *vh1, *vl1;
    u16 *kh2, *kl2, *vh2, *vl2, *kh3, *kl3, *vh3, *vl3;
    float *k1, *v1, *k2, *v2, *k3, *v3;
    cudaGetSymbolAddress((void**)&kh0, g_kh0); cudaGetSymbolAddress((void**)&kl0, g_kl0);
    cudaGetSymbolAddress((void**)&vh0, g_vh0); cudaGetSymbolAddress((void**)&vl0, g_vl0);
    cudaGetSymbolAddress((void**)&kh1, g_kh1); cudaGetSymbolAddress((void**)&kl1, g_kl1);
    cudaGetSymbolAddress((void**)&vh1, g_vh1); cudaGetSymbolAddress((void**)&vl1, g_vl1);
    cudaGetSymbolAddress((void**)&kh2, g_kh2); cudaGetSymbolAddress((void**)&kl2, g_kl2);
    cudaGetSymbolAddress((void**)&vh2, g_vh2); cudaGetSymbolAddress((void**)&vl2, g_vl2);
    cudaGetSymbolAddress((void**)&kh3, g_kh3); cudaGetSymbolAddress((void**)&kl3, g_kl3);
    cudaGetSymbolAddress((void**)&vh3, g_vh3); cudaGetSymbolAddress((void**)&vl3, g_vl3);
    cudaGetSymbolAddress((void**)&k1, g_k1);   cudaGetSymbolAddress((void**)&v1, g_v1);
    cudaGetSymbolAddress((void**)&k2, g_k2);   cudaGetSymbolAddress((void**)&v2, g_v2);
    cudaGetSymbolAddress((void**)&k3, g_k3);   cudaGetSymbolAddress((void**)&v3, g_v3);

    fuse_kernel<<<dim3(NN / 32, HH), 256>>>(k, v, NN, kh0, kl0, vh0, vl0, k1, v1);
    fuse_kernel<<<dim3(1024 / 32, HH), 256>>>(k1, v1, 1024, kh1, kl1, vh1, vl1, k2, v2);
    fuse_kernel<<<dim3(128 / 32, HH), 256>>>(k2, v2, 128, kh2, kl2, vh2, vl2, k3, v3);
    fuse_kernel<<<dim3(1, HH), 256>>>(k3, v3, 16, kh3, kl3, vh3, vl3, nullptr, nullptr);

    cudaFuncSetAttribute(attn_kernel, cudaFuncAttributeMaxDynamicSharedMemorySize,
                         SMEM_BYTES);
    dim3 grid(NN / 128, HH);
    attn_kernel<<<grid, 128, SMEM_BYTES>>>(q, gammas, out);
}

// round 16
// speedup vs baseline: 1.1784x; 1.1784x over previous
#include <cuda_runtime.h>
#include <cuda_fp16.h>

#define HH 16
#define NN 8192
#define DD 64
#define WW 128
#define NEGV (-1e30f)
#define RS 36          // words per smem plane row (32 data + 4 pad)
#define PLANE 2304     // u32 per plane (64 rows * 36)
#define BUFU 9216      // u32 per buffer (4 planes)
#define SMEM_BYTES (2 * BUFU * 4)

typedef unsigned short u16;
typedef unsigned int u32;

// ---------------- fp32 pooled intermediates ----------------
__device__ float g_k1[HH * 1024 * DD];
__device__ float g_v1[HH * 1024 * DD];
__device__ float g_k2[HH * 128 * DD];
__device__ float g_v2[HH * 128 * DD];
__device__ float g_k3[HH * 16 * DD];
__device__ float g_v3[HH * 16 * DD];

// ---------------- fp16 hi/lo split planes ----------------
// K planes: [h][key][d] (d-major). V planes: [h][d][key] (transposed).
__device__ u16 g_kh0[HH * NN * DD],   g_kl0[HH * NN * DD];
__device__ u16 g_vh0[HH * DD * NN],   g_vl0[HH * DD * NN];
__device__ u16 g_kh1[HH * 1024 * DD], g_kl1[HH * 1024 * DD];
__device__ u16 g_vh1[HH * DD * 1024], g_vl1[HH * DD * 1024];
__device__ u16 g_kh2[HH * 128 * DD],  g_kl2[HH * 128 * DD];
__device__ u16 g_vh2[HH * DD * 128],  g_vl2[HH * DD * 128];
__device__ u16 g_kh3[HH * 16 * DD],   g_kl3[HH * 16 * DD];
__device__ u16 g_vh3[HH * DD * 16],   g_vl3[HH * DD * 16];

// ---------------- helpers ----------------
__device__ __forceinline__ void mma_f16(
    float& d0, float& d1, float& d2, float& d3,
    u32 a0, u32 a1, u32 a2, u32 a3, u32 b0, u32 b1)
{
    asm volatile(
        "mma.sync.aligned.m16n8k16.row.col.f32.f16.f16.f32 "
        "{%0,%1,%2,%3}, {%4,%5,%6,%7}, {%8,%9}, {%0,%1,%2,%3};\n"
        : "+f"(d0), "+f"(d1), "+f"(d2), "+f"(d3)
        : "r"(a0), "r"(a1), "r"(a2), "r"(a3), "r"(b0), "r"(b1));
}

// pack two f32 -> f16x2 (e0 in low 16 bits)
__device__ __forceinline__ u32 packh(float e0, float e1) {
    u32 r; asm("cvt.rn.f16x2.f32 %0, %1, %2;" : "=r"(r) : "f"(e1), "f"(e0));
    return r;
}
// split pair into hi f16x2 + lo f16x2 (residual)
__device__ __forceinline__ void split2h(float x0, float x1, u32& hi, u32& lo) {
    hi = packh(x0, x1);
    u16 b0 = (u16)(hi & 0xffffu), b1 = (u16)(hi >> 16);
    float h0 = __half2float(*reinterpret_cast<__half*>(&b0));
    float h1 = __half2float(*reinterpret_cast<__half*>(&b1));
    lo = packh(x0 - h0, x1 - h1);
}

__device__ __forceinline__ void cp16(const void* smem_dst, const void* gsrc) {
    unsigned sa = (unsigned)__cvta_generic_to_shared(smem_dst);
    asm volatile("cp.async.cg.shared.global [%0], [%1], 16;" :: "r"(sa), "l"(gsrc));
}
__device__ __forceinline__ void cp_commit() {
    asm volatile("cp.async.commit_group;" ::: "memory");
}
__device__ __forceinline__ void cp_wait_all() {
    asm volatile("cp.async.wait_group 0;" ::: "memory");
}

// ---------------- fused split + transpose + pool kernel ----------------
__global__ void fuse_kernel(const float* __restrict__ ksrc,
                            const float* __restrict__ vsrc, int C,
                            u16* __restrict__ khi, u16* __restrict__ klo,
                            u16* __restrict__ vhi, u16* __restrict__ vlo,
                            float* __restrict__ kpool, float* __restrict__ vpool)
{
    __shared__ float skf[32][65], svf[32][65];
    int h = blockIdx.y, k0 = blockIdx.x * 32;
    int tid = threadIdx.x;
#pragma unroll
    for (int it = 0; it < 2; it++) {
        int e = tid + it * 256;
        int row = e >> 4, f4 = e & 15;
        float4 a = make_float4(0.f, 0.f, 0.f, 0.f), b = a;
        if (k0 + row < C) {
            a = reinterpret_cast<const float4*>(ksrc + ((size_t)h * C + k0 + row) * DD)[f4];
            b = reinterpret_cast<const float4*>(vsrc + ((size_t)h * C + k0 + row) * DD)[f4];
        }
        skf[row][f4 * 4 + 0] = a.x; skf[row][f4 * 4 + 1] = a.y;
        skf[row][f4 * 4 + 2] = a.z; skf[row][f4 * 4 + 3] = a.w;
        svf[row][f4 * 4 + 0] = b.x; svf[row][f4 * 4 + 1] = b.y;
        svf[row][f4 * 4 + 2] = b.z; svf[row][f4 * 4 + 3] = b.w;
    }
    __syncthreads();
#pragma unroll
    for (int it = 0; it < 4; it++) {
        int idx = tid + it * 256;
        int key = idx >> 5, dp = (idx & 31) * 2;
        if (k0 + key < C) {
            u32 hi, lo;
            split2h(skf[key][dp], skf[key][dp + 1], hi, lo);
            size_t w = ((size_t)h * C + k0 + key) * 32 + (idx & 31);
            reinterpret_cast<u32*>(khi)[w] = hi;
            reinterpret_cast<u32*>(klo)[w] = lo;
        }
    }
#pragma unroll
    for (int it = 0; it < 4; it++) {
        int idx = tid + it * 256;
        int d = idx >> 4, kp = (idx & 15) * 2;
        if (k0 + kp < C) {
            u32 hi, lo;
            split2h(svf[kp][d], svf[kp + 1][d], hi, lo);
            size_t w = (((size_t)h * DD + d) * C + k0 + kp) >> 1;
            reinterpret_cast<u32*>(vhi)[w] = hi;
            reinterpret_cast<u32*>(vlo)[w] = lo;
        }
    }
    if (kpool != nullptr) {
        int chunk = tid >> 6, d = tid & 63;
        float sk = 0.f, sv = 0.f;
#pragma unroll
        for (int r = 0; r < 8; r++) {
            sk += skf[chunk * 8 + r][d];
            sv += svf[chunk * 8 + r][d];
        }
        size_t w = ((size_t)h * (C / 8) + (k0 >> 3) + chunk) * DD + d;
        kpool[w] = sk * 0.125f;
        vpool[w] = sv * 0.125f;
    }
}

// ---------------- 64-key tile prefetch (256 threads) ----------------
__device__ __forceinline__ void prefetch64(
    u32* sm, int buf,
    const u16* __restrict__ khg, const u16* __restrict__ klg,
    const u16* __restrict__ vhg, const u16* __restrict__ vlg,
    int C, int tb, int tid)
{
    u32* kh = sm + buf * BUFU;
    u32* kl = kh + PLANE;
    u32* vh = kl + PLANE;
    u32* vl = vh + PLANE;
#pragma unroll
    for (int t = 0; t < 2; t++) {
        int e = tid + t * 256;             // [0, 512)
        int row = e >> 3, ch = e & 7;
        int r = tb + row;
        r = r < 0 ? 0 : (r > C - 1 ? C - 1 : r);
        size_t so = (size_t)r * 32 + ch * 4;
        cp16(kh + row * RS + ch * 4, (const u32*)khg + so);
        cp16(kl + row * RS + ch * 4, (const u32*)klg + so);
    }
#pragma unroll
    for (int t = 0; t < 2; t++) {
        int e = tid + t * 256;             // [0, 512)
        int d = e >> 3, ch = e & 7;
        int k0 = tb + ch * 8;
        k0 = k0 < 0 ? 0 : (k0 > C - 8 ? C - 8 : k0);
        size_t so = ((size_t)d * C + k0) >> 1;
        cp16(vh + d * RS + ch * 4, (const u32*)vhg + so);
        cp16(vl + d * RS + ch * 4, (const u32*)vlg + so);
    }
    cp_commit();
}

// ---------------- FA2 fp16-split attention ----------------
// CTA = 128 queries x 1 head; 8 warps x 16 rows; m16n8k16 f16.
// 2-term scheme: QK = qh*(kh + kl)  (Q single fp16, K split);
//                PV = Pf*(vh + vl)  (P single fp16, V split).

__global__ void __launch_bounds__(256, 2) attn_kernel(
    const float* __restrict__ q, const float* __restrict__ gammas,
    float* __restrict__ out)
{
    extern __shared__ u32 sm[];

    int h = blockIdx.y;
    int qtile = (int)(gridDim.x - 1u - blockIdx.x);   // heavy tiles first
    int qs = qtile * 128;
    int tid = threadIdx.x;
    int warp = tid >> 5, lane = tid & 31;
    int r0 = qs + warp * 16;
    int g = lane >> 2, c = lane & 3;
    int cc = 2 * c;
    int i0 = r0 + g, i1 = i0 + 8;

    // Q -> single fp16 fragments (no lo term needed)
    u32 qh[4][4];
    {
        const float* q0p = q + ((size_t)h * NN + i0) * DD;
        const float* q1p = q + ((size_t)h * NN + i1) * DD;
#pragma unroll
        for (int ks = 0; ks < 4; ks++) {
            qh[ks][0] = packh(q0p[16 * ks + cc],     q0p[16 * ks + cc + 1]);
            qh[ks][1] = packh(q1p[16 * ks + cc],     q1p[16 * ks + cc + 1]);
            qh[ks][2] = packh(q0p[16 * ks + cc + 8], q0p[16 * ks + cc + 9]);
            qh[ks][3] = packh(q1p[16 * ks + cc + 8], q1p[16 * ks + cc + 9]);
        }
    }

    float m0 = NEGV, m1 = NEGV, l0 = 0.f, l1 = 0.f;
    float O[8][4];
#pragma unroll
    for (int n = 0; n < 8; n++) { O[n][0] = O[n][1] = O[n][2] = O[n][3] = 0.f; }

    float gm[4] = { __ldg(&gammas[0]), __ldg(&gammas[1]),
                    __ldg(&gammas[2]), __ldg(&gammas[3]) };
    const float scale = 0.125f;

    auto do_half = [&](const u32* kbh, const u32* kbl, const u32* vbh, const u32* vbl,
                       bool L0, int base, int S, float gamma) {
        float s[4][4];
#pragma unroll
        for (int n = 0; n < 4; n++) { s[n][0] = s[n][1] = s[n][2] = s[n][3] = 0.f; }

        // ---- QK^T: 4 n-steps x 4 k-steps x 2 MMA ----
#pragma unroll
        for (int nb = 0; nb < 4; nb++) {
            const u32* ph = kbh + (nb * 8 + g) * RS + c;
            const u32* pl = kbl + (nb * 8 + g) * RS + c;
#pragma unroll
            for (int ks = 0; ks < 4; ks++) {
                u32 bh0 = ph[8 * ks], bh1 = ph[8 * ks + 4];
                u32 bl0 = pl[8 * ks], bl1 = pl[8 * ks + 4];
                mma_f16(s[nb][0], s[nb][1], s[nb][2], s[nb][3],
                        qh[ks][0], qh[ks][1], qh[ks][2], qh[ks][3], bh0, bh1);
                mma_f16(s[nb][0], s[nb][1], s[nb][2], s[nb][3],
                        qh[ks][0], qh[ks][1], qh[ks][2], qh[ks][3], bl0, bl1);
            }
        }

        // ---- mask + ALiBi bias ----
#pragma unroll
        for (int n = 0; n < 4; n++) {
            int colA = 8 * n + cc;
            if (L0) {
                int jA = base + colA, jB = jA + 1;
                int dA0 = i0 - jA, dB0 = dA0 - 1;
                int dA1 = dA0 + 8, dB1 = dA1 - 1;
                s[n][0] = (jA >= 0 && (unsigned)dA0 < WW) ? fmaf(s[n][0], scale, -gamma * (float)dA0) : NEGV;
                s[n][1] = (jB >= 0 && (unsigned)dB0 < WW) ? fmaf(s[n][1], scale, -gamma * (float)dB0) : NEGV;
                s[n][2] = (jA >= 0 && (unsigned)dA1 < WW) ? fmaf(s[n][2], scale, -gamma * (float)dA1) : NEGV;
                s[n][3] = (jB >= 0 && (unsigned)dB1 < WW) ? fmaf(s[n][3], scale, -gamma * (float)dB1) : NEGV;
            } else {
                int jlA = (base + colA + 1) * S - 1;
                int jlB = jlA + S;
                int dA0 = i0 - jlA, dB0 = i0 - jlB;
                int dA1 = dA0 + 8, dB1 = dB0 + 8;
                s[n][0] = (dA0 >= WW) ? fmaf(s[n][0], scale, -gamma * (float)dA0) : NEGV;
                s[n][1] = (dB0 >= WW) ? fmaf(s[n][1], scale, -gamma * (float)dB0) : NEGV;
                s[n][2] = (dA1 >= WW) ? fmaf(s[n][2], scale, -gamma * (float)dA1) : NEGV;
                s[n][3] = (dB1 >= WW) ? fmaf(s[n][3], scale, -gamma * (float)dB1) : NEGV;
            }
        }

        // ---- online softmax ----
        float ml0 = s[0][0], ml1 = s[0][2];
#pragma unroll
        for (int n = 0; n < 4; n++) {
            ml0 = fmaxf(ml0, fmaxf(s[n][0], s[n][1]));
            ml1 = fmaxf(ml1, fmaxf(s[n][2], s[n][3]));
        }
        ml0 = fmaxf(ml0, __shfl_xor_sync(0xffffffffu, ml0, 1));
        ml0 = fmaxf(ml0, __shfl_xor_sync(0xffffffffu, ml0, 2));
        ml1 = fmaxf(ml1, __shfl_xor_sync(0xffffffffu, ml1, 1));
        ml1 = fmaxf(ml1, __shfl_xor_sync(0xffffffffu, ml1, 2));
        float nm0 = fmaxf(m0, ml0), nm1 = fmaxf(m1, ml1);
        float e0 = __expf(m0 - nm0), e1 = __expf(m1 - nm1);
        m0 = nm0; m1 = nm1;
        float sum0 = 0.f, sum1 = 0.f;
#pragma unroll
        for (int n = 0; n < 4; n++) {
            s[n][0] = __expf(s[n][0] - nm0); sum0 += s[n][0];
            s[n][1] = __expf(s[n][1] - nm0); sum0 += s[n][1];
            s[n][2] = __expf(s[n][2] - nm1); sum1 += s[n][2];
            s[n][3] = __expf(s[n][3] - nm1); sum1 += s[n][3];
        }
        l0 = fmaf(l0, e0, sum0);
        l1 = fmaf(l1, e1, sum1);
        if (!__all_sync(0xffffffffu, (e0 == 1.f) && (e1 == 1.f))) {
#pragma unroll
            for (int n = 0; n < 8; n++) {
                O[n][0] *= e0; O[n][1] *= e0; O[n][2] *= e1; O[n][3] *= e1;
            }
        }

        // ---- O += P V : P single fp16, 2 k-steps x 8 n-steps x 2 MMA ----
#pragma unroll
        for (int kt = 0; kt < 2; kt++) {
            u32 A[4];
            A[0] = packh(s[2 * kt][0],     s[2 * kt][1]);
            A[1] = packh(s[2 * kt][2],     s[2 * kt][3]);
            A[2] = packh(s[2 * kt + 1][0], s[2 * kt + 1][1]);
            A[3] = packh(s[2 * kt + 1][2], s[2 * kt + 1][3]);
#pragma unroll
            for (int nb = 0; nb < 8; nb++) {
                const u32* ph = vbh + (nb * 8 + g) * RS + c;
                const u32* pl = vbl + (nb * 8 + g) * RS + c;
                u32 bh0 = ph[8 * kt], bh1 = ph[8 * kt + 4];
                u32 bl0 = pl[8 * kt], bl1 = pl[8 * kt + 4];
                mma_f16(O[nb][0], O[nb][1], O[nb][2], O[nb][3],
                        A[0], A[1], A[2], A[3], bh0, bh1);
                mma_f16(O[nb][0], O[nb][1], O[nb][2], O[nb][3],
                        A[0], A[1], A[2], A[3], bl0, bl1);
            }
        }
    };

#pragma unroll 1
    for (int lvl = 0; lvl < 4; lvl++) {
        const u16 *khg, *klg, *vhg, *vlg;
        int C, S, n, ntv = 0;
        float gamma = gm[lvl];
        bool L0 = (lvl == 0);
        if (lvl == 0) {
            khg = g_kh0 + (size_t)h * NN * DD;  klg = g_kl0 + (size_t)h * NN * DD;
            vhg = g_vh0 + (size_t)h * DD * NN;  vlg = g_vl0 + (size_t)h * DD * NN;
            C = NN; S = 1;
            n = qs / 64 + 2; if (n > 4) n = 4;
        } else {
            if (lvl == 1) {
                khg = g_kh1 + (size_t)h * 1024 * DD; klg = g_kl1 + (size_t)h * 1024 * DD;
                vhg = g_vh1 + (size_t)h * DD * 1024; vlg = g_vl1 + (size_t)h * DD * 1024;
                C = 1024; S = 8;
            } else if (lvl == 2) {
                khg = g_kh2 + (size_t)h * 128 * DD;  klg = g_kl2 + (size_t)h * 128 * DD;
                vhg = g_vh2 + (size_t)h * DD * 128;  vlg = g_vl2 + (size_t)h * DD * 128;
                C = 128; S = 64;
            } else {
                khg = g_kh3 + (size_t)h * 16 * DD;   klg = g_kl3 + (size_t)h * 16 * DD;
                vhg = g_vh3 + (size_t)h * DD * 16;   vlg = g_vl3 + (size_t)h * DD * 16;
                C = 16; S = 512;
            }
            int cmax = qs / S - 1;
            if (cmax < 0) { continue; }
            ntv = cmax / 64 + 1;
            int dcut = (int)(24.0f / gamma);     // ALiBi horizon (err < e^-20)
            n = 0;
#pragma unroll 1
            for (int it = 0; it < ntv; it++) {
                int cb = (ntv - 1 - it) * 64;
                if (qs - ((cb + 64) * S - 1) <= dcut) n++;
                else break;
            }
            if (n <= 0) continue;
        }

        int cwmax = 0x7fffffff;
        if (!L0) cwmax = (r0 >= 112 + S) ? ((r0 - 112) / S - 1) : -1;
        int dcutw = L0 ? 0 : (int)(24.0f / gamma);

        __syncthreads();            // previous level's buffers done
        int tb0 = L0 ? (qs + 128 - 64) : ((ntv - 1) * 64);
        prefetch64(sm, 0, khg, klg, vhg, vlg, C, tb0, tid);
#pragma unroll 1
        for (int it = 0; it < n; it++) {
            int buf = it & 1;
            int tb = L0 ? (qs + 128 - 64 * (it + 1)) : ((ntv - 1 - it) * 64);
            cp_wait_all();
            __syncthreads();
            if (it + 1 < n) {
                int tb1 = L0 ? (qs + 128 - 64 * (it + 2)) : ((ntv - 2 - it) * 64);
                prefetch64(sm, (it + 1) & 1, khg, klg, vhg, vlg, C, tb1, tid);
            }
            const u32* kb = sm + buf * BUFU;
            const u32* klb = kb + PLANE;
            const u32* vb = klb + PLANE;
            const u32* vlb = vb + PLANE;
            // two 32-key halves, nearest (higher keys) first
#pragma unroll
            for (int hf = 1; hf >= 0; hf--) {
                int base = tb + 32 * hf;
                if (L0) {
                    if (base > r0 + 15 || base + 31 < r0 - (WW - 1)) continue;
                } else {
                    if (base > cwmax) continue;
                    if (r0 - ((base + 32) * S - 1) > dcutw) continue;
                }
                do_half(kb + hf * 32 * RS, klb + hf * 32 * RS,
                        vb + hf * 16, vlb + hf * 16, L0, base, S, gamma);
            }
        }
    }

    // ================= epilogue: out = O / clip(l, 1e-8) =================
    l0 += __shfl_xor_sync(0xffffffffu, l0, 1);
    l0 += __shfl_xor_sync(0xffffffffu, l0, 2);
    l1 += __shfl_xor_sync(0xffffffffu, l1, 1);
    l1 += __shfl_xor_sync(0xffffffffu, l1, 2);
    float inv0 = 1.0f / fmaxf(l0, 1e-8f);
    float inv1 = 1.0f / fmaxf(l1, 1e-8f);
    float* o0p = out + ((size_t)h * NN + i0) * DD;
    float* o1p = out + ((size_t)h * NN + i1) * DD;
#pragma unroll
    for (int n = 0; n < 8; n++) {
        float2 w0 = make_float2(O[n][0] * inv0, O[n][1] * inv0);
        float2 w1 = make_float2(O[n][2] * inv1, O[n][3] * inv1);
        *reinterpret_cast<float2*>(o0p + 8 * n + cc) = w0;
        *reinterpret_cast<float2*>(o1p + 8 * n + cc) = w1;
    }
}

// ---------------- launch ----------------
extern "C" void kernel_launch(void* const* d_in, const int* in_sizes, int n_in,
                              void* d_out, int out_size) {
    const float* q      = (const float*)d_in[0];
    const float* k      = (const float*)d_in[1];
    const float* v      = (const float*)d_in[2];
    const float* gammas = (const float*)d_in[3];
    float* out = (float*)d_out;

    u16 *kh0, *kl0, *vh0, *vl0, *kh1, *kl1, *vh1, *vl1;
    u16 *kh2, *kl2, *vh2, *vl2, *kh3, *kl3, *vh3, *vl3;
    float *k1, *v1, *k2, *v2, *k3, *v3;
    cudaGetSymbolAddress((void**)&kh0, g_kh0); cudaGetSymbolAddress((void**)&kl0, g_kl0);
    cudaGetSymbolAddress((void**)&vh0, g_vh0); cudaGetSymbolAddress((void**)&vl0, g_vl0);
    cudaGetSymbolAddress((void**)&kh1, g_kh1); cudaGetSymbolAddress((void**)&kl1, g_kl1);
    cudaGetSymbolAddress((void**)&vh1, g_vh1); cudaGetSymbolAddress((void**)&vl1, g_vl1);
    cudaGetSymbolAddress((void**)&kh2, g_kh2); cudaGetSymbolAddress((void**)&kl2, g_kl2);
    cudaGetSymbolAddress((void**)&vh2, g_vh2); cudaGetSymbolAddress((void**)&vl2, g_vl2);
    cudaGetSymbolAddress((void**)&kh3, g_kh3); cudaGetSymbolAddress((void**)&kl3, g_kl3);
    cudaGetSymbolAddress((void**)&vh3, g_vh3); cudaGetSymbolAddress((void**)&vl3, g_vl3);
    cudaGetSymbolAddress((void**)&k1, g_k1);   cudaGetSymbolAddress((void**)&v1, g_v1);
    cudaGetSymbolAddress((void**)&k2, g_k2);   cudaGetSymbolAddress((void**)&v2, g_v2);
    cudaGetSymbolAddress((void**)&k3, g_k3);   cudaGetSymbolAddress((void**)&v3, g_v3);

    fuse_kernel<<<dim3(NN / 32, HH), 256>>>(k, v, NN, kh0, kl0, vh0, vl0, k1, v1);
    fuse_kernel<<<dim3(1024 / 32, HH), 256>>>(k1, v1, 1024, kh1, kl1, vh1, vl1, k2, v2);
    fuse_kernel<<<dim3(128 / 32, HH), 256>>>(k2, v2, 128, kh2, kl2, vh2, vl2, k3, v3);
    fuse_kernel<<<dim3(1, HH), 256>>>(k3, v3, 16, kh3, kl3, vh3, vl3, nullptr, nullptr);

    cudaFuncSetAttribute(attn_kernel, cudaFuncAttributeMaxDynamicSharedMemorySize,
                         SMEM_BYTES);
    dim3 grid(NN / 128, HH);
    attn_kernel<<<grid, 256, SMEM_BYTES>>>(q, gammas, out);
}